// round 14
// baseline (speedup 1.0000x reference)
#include <cuda_runtime.h>
#include <cstdint>

// x:      (16, 16, 64, 512)  f32
// kernel: (32, 16, 4)        f32
// points: (16, 3, 64, 512)   f32
// out:    (16, 32, 62, 510)  f32
#define CH_STRIDE 32768
#define HP 62
#define WP 510
#define OUT_PLANE (62*510)
#define KSTR 72
#define DSTR 260
#define KSM_OFF 16384           // Cs words before Ksm

typedef unsigned long long u64;
typedef unsigned int u32;

__device__ __forceinline__ u64 pk(float lo, float hi) {
    u64 r; asm("mov.b64 %0, {%1,%2};" : "=l"(r) : "f"(lo), "f"(hi)); return r;
}
__device__ __forceinline__ void upk(u64 v, float& lo, float& hi) {
    asm("mov.b64 {%0,%1}, %2;" : "=f"(lo), "=f"(hi) : "l"(v));
}
__device__ __forceinline__ u64 fma2(u64 a, u64 b, u64 c) {
    u64 d; asm("fma.rn.f32x2 %0, %1, %2, %3;" : "=l"(d) : "l"(a), "l"(b), "l"(c)); return d;
}
__device__ __forceinline__ u64 add2(u64 a, u64 b) {
    u64 d; asm("add.rn.f32x2 %0, %1, %2;" : "=l"(d) : "l"(a), "l"(b)); return d;
}
__device__ __forceinline__ u64 neg2(u64 a) { return a ^ 0x8000000080000000ULL; }

__device__ __forceinline__ u32 tf32r(float f) {
    u32 r; asm("cvt.rna.tf32.f32 %0, %1;" : "=r"(r) : "f"(f)); return r;
}

__device__ __forceinline__ void mma_tf32(float& d0, float& d1, float& d2, float& d3,
                                         u32 a0, u32 a1, u32 a2, u32 a3,
                                         u32 b0, u32 b1) {
    asm volatile("mma.sync.aligned.m16n8k8.row.col.f32.tf32.tf32.f32 "
                 "{%0,%1,%2,%3}, {%4,%5,%6,%7}, {%8,%9}, {%0,%1,%2,%3};"
                 : "+f"(d0), "+f"(d1), "+f"(d2), "+f"(d3)
                 : "r"(a0), "r"(a1), "r"(a2), "r"(a3), "r"(b0), "r"(b1));
}

extern __shared__ u32 smw[];

__global__ void __launch_bounds__(256, 3)
flex_conv_mma9_kernel(const float* __restrict__ x,
                      const float* __restrict__ kern,
                      const float* __restrict__ pts,
                      float* __restrict__ out)
{
    // Cs: 256 rows x 64 words. Row rho: rho(2m)=m, rho(2m+1)=m+128 (pixel-pair
    // halves split top/bottom). Group swizzle pr^(row&7); within group, logical
    // word v at physical v ^ (4*((row>>2)&1)); pair-interleave so the MMA
    // A-frag (k=cq, k=cq+4) is one uint2. Ksm appended, fragment-pair order.
    u32* Cs  = smw;
    u32* Ksm = smw + KSM_OFF;

    const int tid = threadIdx.x;

    #pragma unroll
    for (int t = 0; t < 8; ++t) {
        int idx = t * 256 + tid;           // o*64 + c
        int o = idx >> 6, c = idx & 63;
        int pos = 2 * (c & 3) + ((c >> 2) & 1);
        Ksm[o * KSTR + (c >> 3) * 8 + pos] = tf32r(kern[idx]);
    }

    const int m   = tid & 127;           // pixel-pair index in tile
    const int cg  = tid >> 7;            // 0: ch 0-7, 1: ch 8-15
    const int wpx = blockIdx.x * 256 + 2 * m;
    const int wb  = (wpx < 508) ? wpx : 508;   // clamp only affects masked pixels
    const int h   = blockIdx.y;
    const int b   = blockIdx.z;

    const float* xb  = x   + ((b * 16 + cg * 8) * 64 + h) * 512 + wb;
    const float* pbb = pts + ((b * 3) * 64 + h) * 512 + wb;

    const int h2 = (m >> 2) & 1;
    u32* crow = Cs + m * 64;

    // ---------------- phase 1: box sums, pixels in f32x2 lanes ----------------
    #pragma unroll 1
    for (int pass = 0; pass < 2; ++pass) {
        u64 A2[4], Bn[3][4], ctr[3];
        #pragma unroll
        for (int j = 0; j < 4; ++j) { A2[j] = 0ull; Bn[0][j] = 0ull; Bn[1][j] = 0ull; Bn[2][j] = 0ull; }

        #pragma unroll
        for (int r = 0; r < 3; ++r) {
            u64 q0[3], q1[3], q2[3];
            #pragma unroll
            for (int d = 0; d < 3; ++d) {
                const float* pp = pbb + d * CH_STRIDE + r * 512;
                float2 pA = *reinterpret_cast<const float2*>(pp);
                float2 pB = *reinterpret_cast<const float2*>(pp + 2);
                q0[d] = pk(pA.x, pA.y);
                q1[d] = pk(pA.y, pB.x);
                q2[d] = pk(pB.x, pB.y);
                if (r == 1) ctr[d] = q1[d];   // centers = pts[h+1][w+1] per lane
            }
            #pragma unroll
            for (int j = 0; j < 4; ++j) {
                const float* xc = xb + (pass * 4 + j) * CH_STRIDE + r * 512;
                float2 xA = *reinterpret_cast<const float2*>(xc);
                float2 xB = *reinterpret_cast<const float2*>(xc + 2);
                u64 f0 = pk(xA.x, xA.y);
                u64 f1 = pk(xA.y, xB.x);
                u64 f2 = pk(xB.x, xB.y);
                A2[j] = add2(A2[j], add2(add2(f0, f1), f2));
                #pragma unroll
                for (int d = 0; d < 3; ++d)
                    Bn[d][j] = fma2(q2[d], f2, fma2(q1[d], f1, fma2(q0[d], f0, Bn[d][j])));
            }
        }

        // C = ctr*A - B (per lane = per pixel); A appended as homogeneous term
        u64 C0[4], C1[4], C2[4];
        #pragma unroll
        for (int j = 0; j < 4; ++j) {
            C0[j] = fma2(ctr[0], A2[j], neg2(Bn[0][j]));
            C1[j] = fma2(ctr[1], A2[j], neg2(Bn[1][j]));
            C2[j] = fma2(ctr[2], A2[j], neg2(Bn[2][j]));
        }

        #pragma unroll
        for (int gi = 0; gi < 2; ++gi) {
            const int j0 = 2 * gi, j1 = 2 * gi + 1;
            const int pr = cg * 4 + pass * 2 + gi;
            float a0l,a0h,a1l,a1h, b0l,b0h,b1l,b1h, c0l,c0h,c1l,c1h, s0l,s0h,s1l,s1h;
            upk(C0[j0], a0l, a0h); upk(C0[j1], a1l, a1h);
            upk(C1[j0], b0l, b0h); upk(C1[j1], b1l, b1h);
            upk(C2[j0], c0l, c0h); upk(C2[j1], c1l, c1h);
            upk(A2[j0], s0l, s0h); upk(A2[j1], s1l, s1h);

            u32* p = crow + ((pr ^ (m & 7)) << 3);
            // row m  <- lane-lo (pixel 2m)
            *reinterpret_cast<uint4*>(p + 4 * h2) =
                make_uint4(tf32r(a0l), tf32r(a1l), tf32r(b0l), tf32r(b1l));
            *reinterpret_cast<uint4*>(p + (4 * h2 ^ 4)) =
                make_uint4(tf32r(c0l), tf32r(c1l), tf32r(s0l), tf32r(s1l));
            // row m+128 <- lane-hi (pixel 2m+1); same swizzle (row&7, row>>2 parity match)
            *reinterpret_cast<uint4*>(p + 128 * 64 + 4 * h2) =
                make_uint4(tf32r(a0h), tf32r(a1h), tf32r(b0h), tf32r(b1h));
            *reinterpret_cast<uint4*>(p + 128 * 64 + (4 * h2 ^ 4)) =
                make_uint4(tf32r(c0h), tf32r(c1h), tf32r(s0h), tf32r(s1h));
        }
    }
    __syncthreads();

    // ---------------- phase 2: out[256px, 32o] = C[256x64] * K^T (8 warps) ----------------
    const int lane  = tid & 31;
    const int wq    = tid >> 5;
    const int g     = lane >> 2;
    const int cq    = lane & 3;
    const int g2    = (g >> 2) & 1;
    const int rbase = wq * 32;           // warp's 32-row slab

    float dd[2][4][4];
    #pragma unroll
    for (int mt = 0; mt < 2; ++mt)
        #pragma unroll
        for (int nt = 0; nt < 4; ++nt)
            #pragma unroll
            for (int e = 0; e < 4; ++e) dd[mt][nt][e] = 0.0f;

    #pragma unroll
    for (int kt = 0; kt < 8; ++kt) {
        uint2 bf[4];
        #pragma unroll
        for (int nt = 0; nt < 4; ++nt)
            bf[nt] = *reinterpret_cast<const uint2*>(Ksm + (nt * 8 + g) * KSTR + kt * 8 + 2 * cq);

        #pragma unroll
        for (int mt = 0; mt < 2; ++mt) {
            const int r0 = rbase + mt * 16 + g;          // r0&7==g, (r0>>2)&1==g2
            const u32* ap = Cs + r0 * 64 + ((kt ^ g) << 3) + ((2 * cq) ^ (4 * g2));
            uint2 v0 = *reinterpret_cast<const uint2*>(ap);
            uint2 v1 = *reinterpret_cast<const uint2*>(ap + 8 * 64);
            #pragma unroll
            for (int nt = 0; nt < 4; ++nt)
                mma_tf32(dd[mt][nt][0], dd[mt][nt][1], dd[mt][nt][2], dd[mt][nt][3],
                         v0.x, v1.x, v0.y, v1.y, bf[nt].x, bf[nt].y);
        }
    }
    __syncthreads();   // Cs free -> reuse as Dsm[o][w_local], stride DSTR

    // scatter: row rho -> w_local = 2*(rho&127) + (rho>>7)
    #pragma unroll
    for (int mt = 0; mt < 2; ++mt) {
        const int rA  = rbase + mt * 16 + g;
        const int wlA = 2 * (rA & 127) + (rA >> 7);
        const int wlB = wlA + 16;                        // rA+8 -> +16
        #pragma unroll
        for (int nt = 0; nt < 4; ++nt) {
            const int o0 = nt * 8 + 2 * cq;
            Cs[o0 * DSTR + wlA]       = __float_as_uint(dd[mt][nt][0]);
            Cs[(o0 + 1) * DSTR + wlA] = __float_as_uint(dd[mt][nt][1]);
            Cs[o0 * DSTR + wlB]       = __float_as_uint(dd[mt][nt][2]);
            Cs[(o0 + 1) * DSTR + wlB] = __float_as_uint(dd[mt][nt][3]);
        }
    }
    __syncthreads();

    // coalesced stores: warp wq: o = wq*4..wq*4+3; two 128-px halves; lane -> 4 w
    #pragma unroll
    for (int oo = 0; oo < 4; ++oo) {
        const int o = wq * 4 + oo;
        float* obase = out + (b * 32 + o) * OUT_PLANE + h * WP;
        #pragma unroll
        for (int s = 0; s < 2; ++s) {
            const int wloc = s * 128 + lane * 4;
            uint4 v = *reinterpret_cast<const uint4*>(Cs + o * DSTR + wloc);
            const int w0 = blockIdx.x * 256 + wloc;      // even -> float2 aligned
            *reinterpret_cast<float2*>(obase + w0) =
                make_float2(__uint_as_float(v.x), __uint_as_float(v.y));
            if (w0 + 2 < WP)
                *reinterpret_cast<float2*>(obase + w0 + 2) =
                    make_float2(__uint_as_float(v.z), __uint_as_float(v.w));
        }
    }
}

extern "C" void kernel_launch(void* const* d_in, const int* in_sizes, int n_in,
                              void* d_out, int out_size)
{
    const float* x = nullptr; const float* kern = nullptr; const float* pts = nullptr;
    for (int i = 0; i < n_in; ++i) {
        if (in_sizes[i] == 8388608)      x    = (const float*)d_in[i];
        else if (in_sizes[i] == 2048)    kern = (const float*)d_in[i];
        else if (in_sizes[i] == 1572864) pts  = (const float*)d_in[i];
    }
    const int smem_bytes = (KSM_OFF + 32 * KSTR) * 4;   // 74,752 B
    cudaFuncSetAttribute(flex_conv_mma9_kernel,
                         cudaFuncAttributeMaxDynamicSharedMemorySize, smem_bytes);
    dim3 grid(2, 62, 16);   // 2 w-tiles of 256, 62 h rows, batch
    flex_conv_mma9_kernel<<<grid, 256, smem_bytes>>>(x, kern, pts, (float*)d_out);
}